// round 5
// baseline (speedup 1.0000x reference)
#include <cuda_runtime.h>
#include <math.h>

#define HID    768
#define INTER  3072
#define NHEAD  12
#define DH     64
#define NTOK   16384
#define WWIN   256
#define MIDC   5376     // 3*HID + INTER
#define NCHUNK 64       // NTOK / WWIN

// Scratch (device globals: allocation-free rule)
__device__ float g_xn[(size_t)NTOK * HID];           // 48 MB
__device__ float g_mid[(size_t)NTOK * MIDC];         // 352 MB: [q|k|v|ff] -> [attn|k|v|gelu(ff)]

// ---------------- LayerNorm ----------------
__global__ void ln_kernel(const float* __restrict__ x,
                          const float* __restrict__ gamma,
                          const float* __restrict__ beta) {
    const int row = blockIdx.x, t = threadIdx.x;
    const float* xr = x + (size_t)row * HID;
    float v0 = xr[t], v1 = xr[t + 256], v2 = xr[t + 512];
    float s  = v0 + v1 + v2;
    float ss = v0 * v0 + v1 * v1 + v2 * v2;
    #pragma unroll
    for (int o = 16; o; o >>= 1) {
        s  += __shfl_xor_sync(0xffffffffu, s,  o);
        ss += __shfl_xor_sync(0xffffffffu, ss, o);
    }
    __shared__ float sh[18];
    if ((t & 31) == 0) { sh[t >> 5] = s; sh[(t >> 5) + 8] = ss; }
    __syncthreads();
    if (t == 0) {
        float S = 0.f, SS = 0.f;
        #pragma unroll
        for (int i = 0; i < 8; i++) { S += sh[i]; SS += sh[i + 8]; }
        float mu  = S * (1.0f / HID);
        float var = SS * (1.0f / HID) - mu * mu;
        sh[16] = mu;
        sh[17] = rsqrtf(var + 1e-5f);
    }
    __syncthreads();
    const float mu = sh[16], rs = sh[17];
    float* o = g_xn + (size_t)row * HID;
    o[t]       = (v0 - mu) * rs * gamma[t]       + beta[t];
    o[t + 256] = (v1 - mu) * rs * gamma[t + 256] + beta[t + 256];
    o[t + 512] = (v2 - mu) * rs * gamma[t + 512] + beta[t + 512];
}

// ---------------- GEMM: C[M,N] = A[M,K] @ B[K,N] (+epilogue) ----------------
// mode 1: C += bias; gelu on cols >= 3*HID (GEMM1 into g_mid)
// mode 2: A column remap (k>=HID -> k+2*HID, skipping k,v), C = acc + bias + resid (-> d_out)
__global__ __launch_bounds__(256, 2)
void gemm_kernel(const float* __restrict__ A, const float* __restrict__ B,
                 const float* __restrict__ bias, const float* __restrict__ resid,
                 float* __restrict__ C,
                 int K, int lda, int ldb, int ldc, int mode)
{
    __shared__ float As[8][132];
    __shared__ float Bs[8][128];
    const int tid = threadIdx.x;
    const int m0 = blockIdx.y << 7;
    const int n0 = blockIdx.x << 7;
    const int arow = tid >> 1,  acol = (tid & 1) << 2;
    const int brow = tid >> 5,  bcol = (tid & 31) << 2;
    const int tx = (tid & 15) << 3, ty = (tid >> 4) << 3;

    const float* Aptr = A + (size_t)(m0 + arow) * lda;
    const float* Bptr = B + (size_t)brow * ldb + n0 + bcol;

    float acc[8][8];
    #pragma unroll
    for (int i = 0; i < 8; i++)
        #pragma unroll
        for (int j = 0; j < 8; j++) acc[i][j] = 0.f;

    // register prefetch of first tiles
    int ka = acol;
    int kam = (mode == 2 && ka >= HID) ? ka + 2 * HID : ka;
    float4 av = *(const float4*)(Aptr + kam);
    float4 bv = *(const float4*)(Bptr);

    for (int k0 = 0; k0 < K; k0 += 8) {
        As[acol + 0][arow] = av.x;
        As[acol + 1][arow] = av.y;
        As[acol + 2][arow] = av.z;
        As[acol + 3][arow] = av.w;
        *(float4*)&Bs[brow][bcol] = bv;
        __syncthreads();
        const int kn = k0 + 8;
        if (kn < K) {
            int kb = kn + acol;
            int km = (mode == 2 && kb >= HID) ? kb + 2 * HID : kb;
            av = *(const float4*)(Aptr + km);
            bv = *(const float4*)(Bptr + (size_t)kn * ldb);
        }
        #pragma unroll
        for (int kk = 0; kk < 8; kk++) {
            float a[8], b[8];
            *(float4*)&a[0] = *(const float4*)&As[kk][ty];
            *(float4*)&a[4] = *(const float4*)&As[kk][ty + 4];
            *(float4*)&b[0] = *(const float4*)&Bs[kk][tx];
            *(float4*)&b[4] = *(const float4*)&Bs[kk][tx + 4];
            #pragma unroll
            for (int i = 0; i < 8; i++)
                #pragma unroll
                for (int j = 0; j < 8; j++)
                    acc[i][j] = fmaf(a[i], b[j], acc[i][j]);
        }
        __syncthreads();
    }

    float bvv[8];
    #pragma unroll
    for (int j = 0; j < 8; j++) bvv[j] = bias[n0 + tx + j];
    const bool isff = (mode == 1) && (n0 + tx >= 3 * HID);  // 3*HID % 8 == 0: group uniform

    #pragma unroll
    for (int i = 0; i < 8; i++) {
        const size_t m = (size_t)(m0 + ty + i);
        float o[8];
        #pragma unroll
        for (int j = 0; j < 8; j++) {
            float v = acc[i][j] + bvv[j];
            if (isff) {  // tanh-approx gelu (jax.nn.gelu default)
                float u = v * (0.7978845608028654f + 0.0356774081f * v * v);
                v = 0.5f * v * (1.0f + tanhf(u));
            }
            o[j] = v;
        }
        if (mode == 2) {
            const float* rp = resid + m * HID + n0 + tx;
            float4 r0 = *(const float4*)rp;
            float4 r1 = *(const float4*)(rp + 4);
            o[0] += r0.x; o[1] += r0.y; o[2] += r0.z; o[3] += r0.w;
            o[4] += r1.x; o[5] += r1.y; o[6] += r1.z; o[7] += r1.w;
        }
        float* cp = C + m * ldc + n0 + tx;
        *(float4*)cp       = make_float4(o[0], o[1], o[2], o[3]);
        *(float4*)(cp + 4) = make_float4(o[4], o[5], o[6], o[7]);
    }
}

// ---------------- RoPE (in-place on q,k cols of g_mid) ----------------
__global__ void rope_kernel(const float* __restrict__ psin, const float* __restrict__ pcos) {
    const int idx = blockIdx.x * blockDim.x + threadIdx.x;   // NTOK * 768 pairs
    if (idx >= NTOK * 768) return;
    const int row = idx / 768;
    const int p   = idx - row * 768;
    const int col = p << 1;               // 0..1534 (q|k region)
    const int d   = col & (DH - 1);       // even dim within head
    float2* ptr = (float2*)(g_mid + (size_t)row * MIDC + col);
    const float2 eo = *ptr;
    const float c = pcos[row * DH + d];   // repeated: cos[d]==cos[d+1]
    const float s = psin[row * DH + d];
    float2 r;
    r.x = eo.x * c - eo.y * s;
    r.y = eo.y * c + eo.x * s;
    *ptr = r;
}

// ---------------- Sliding-window attention ----------------
// block = (chunk of 256 queries, head); 1 query per thread; online softmax.
// Keys streamed as 8 tiles of 64 covering [q0-256, q0+256).
__global__ __launch_bounds__(256, 1)
void attn_kernel(const int* __restrict__ plen) {
    __shared__ float Ks[64][DH];
    __shared__ float Vs[64][DH];
    const int h   = blockIdx.y;
    const int q0  = blockIdx.x << 8;
    const int tid = threadIdx.x;
    const int qi  = q0 + tid;
    const unsigned lm   = ~((unsigned)(*plen) - 1u);
    const unsigned qseg = (unsigned)qi & lm;

    float q[DH], acc[DH];
    {
        const float* qp = g_mid + (size_t)qi * MIDC + h * DH;
        #pragma unroll
        for (int i = 0; i < 16; i++) *(float4*)&q[i * 4] = *(const float4*)(qp + i * 4);
    }
    #pragma unroll
    for (int i = 0; i < DH; i++) acc[i] = 0.f;
    float m = -1e30f, l = 0.f;

    const int r   = tid >> 2;
    const int sg  = (tid & 3) << 4;
    const int qw0 = q0 + (tid & ~31);   // warp's first query

    for (int t = 0; t < 8; t++) {
        const int kbase = q0 - 256 + t * 64;
        __syncthreads();
        {   // load 64-key K/V tile (4 threads per row)
            const int kj = kbase + r;
            float4* dK = (float4*)&Ks[r][sg];
            float4* dV = (float4*)&Vs[r][sg];
            if (kj >= 0) {
                const float* kp = g_mid + (size_t)kj * MIDC + HID + h * DH + sg;
                const float* vp = kp + HID;
                #pragma unroll
                for (int i = 0; i < 4; i++) dK[i] = ((const float4*)kp)[i];
                #pragma unroll
                for (int i = 0; i < 4; i++) dV[i] = ((const float4*)vp)[i];
            } else {
                const float4 z = make_float4(0.f, 0.f, 0.f, 0.f);
                #pragma unroll
                for (int i = 0; i < 4; i++) { dK[i] = z; dV[i] = z; }
            }
        }
        __syncthreads();
        int jlo = qw0 - 255 - kbase; if (jlo < 0) jlo = 0;     // warp-uniform bounds
        int jhi = qw0 + 31  - kbase; if (jhi > 63) jhi = 63;
        for (int j = jlo; j <= jhi; j++) {
            const int kj  = kbase + j;
            const int dlt = qi - kj;
            const bool valid = (kj >= 0) & (dlt >= 0) & (dlt < WWIN) &
                               (((unsigned)kj & lm) == qseg);
            if (!valid) continue;
            float s = 0.f;
            #pragma unroll
            for (int d4 = 0; d4 < 16; d4++) {
                const float4 kv = *(const float4*)&Ks[j][d4 * 4];
                s += q[d4*4+0]*kv.x + q[d4*4+1]*kv.y + q[d4*4+2]*kv.z + q[d4*4+3]*kv.w;
            }
            s *= 0.125f;   // 1/sqrt(64)
            if (s > m) {
                const float sf = __expf(m - s);
                l *= sf;
                #pragma unroll
                for (int d = 0; d < DH; d++) acc[d] *= sf;
                m = s;
            }
            const float p = __expf(s - m);
            l += p;
            #pragma unroll
            for (int d4 = 0; d4 < 16; d4++) {
                const float4 vv = *(const float4*)&Vs[j][d4 * 4];
                acc[d4*4+0] = fmaf(p, vv.x, acc[d4*4+0]);
                acc[d4*4+1] = fmaf(p, vv.y, acc[d4*4+1]);
                acc[d4*4+2] = fmaf(p, vv.z, acc[d4*4+2]);
                acc[d4*4+3] = fmaf(p, vv.w, acc[d4*4+3]);
            }
        }
    }
    const float inv = 1.f / l;
    float* op = g_mid + (size_t)qi * MIDC + h * DH;   // overwrite q region with attn
    #pragma unroll
    for (int i = 0; i < 16; i++) {
        *(float4*)(op + i * 4) = make_float4(acc[i*4] * inv, acc[i*4+1] * inv,
                                             acc[i*4+2] * inv, acc[i*4+3] * inv);
    }
}

// ---------------- launch ----------------
extern "C" void kernel_launch(void* const* d_in, const int* in_sizes, int n_in,
                              void* d_out, int out_size) {
    const float* x        = (const float*)d_in[0];
    // d_in[1] = normed_ages (unused by the reference)
    const float* psin     = (const float*)d_in[2];
    const float* pcos     = (const float*)d_in[3];
    const float* ln_scale = (const float*)d_in[4];
    const float* ln_off   = (const float*)d_in[5];
    const float* w_in     = (const float*)d_in[6];
    const float* b_in     = (const float*)d_in[7];
    const float* w_out    = (const float*)d_in[8];
    const float* b_out    = (const float*)d_in[9];
    const int*   plen     = (const int*)d_in[10];
    float* out = (float*)d_out;

    float *p_xn = nullptr, *p_mid = nullptr;
    cudaGetSymbolAddress((void**)&p_xn,  g_xn);
    cudaGetSymbolAddress((void**)&p_mid, g_mid);

    ln_kernel<<<NTOK, 256>>>(x, ln_scale, ln_off);

    // mid = xn @ w_in + b_in ; gelu on ff cols
    gemm_kernel<<<dim3(MIDC / 128, NTOK / 128), 256>>>(
        p_xn, w_in, b_in, nullptr, p_mid, HID, HID, MIDC, MIDC, 1);

    rope_kernel<<<(NTOK * 768) / 256, 256>>>(psin, pcos);

    attn_kernel<<<dim3(NCHUNK, NHEAD), 256>>>(plen);

    // out = xn + [attn | gelu_ff] @ w_out + b_out
    gemm_kernel<<<dim3(HID / 128, NTOK / 128), 256>>>(
        p_mid, w_out, b_out, p_xn, out, HID + INTER, MIDC, HID, HID, 2);
}

// round 7
// speedup vs baseline: 2.1403x; 2.1403x over previous
#include <cuda_runtime.h>
#include <cuda_bf16.h>
#include <math.h>
#include <stdint.h>

#define HID    768
#define INTER  3072
#define NHEAD  12
#define DH     64
#define NTOK   16384
#define WWIN   256
#define NCHUNK 64            // NTOK / WWIN
#define K1     (3 * HID)     // 2304  (tripled K for GEMM1)
#define KC2    (HID + INTER) // 3840  combined cols
#define K2     (3 * KC2)     // 11520 (tripled K for GEMM2)
#define QKVC   (3 * HID)     // 2304 fp32 qkv cols

// ---------------- scratch (device globals; allocation-free rule) ----------------
__device__ __align__(256) float          g_xn  [(size_t)NTOK * HID];
__device__ __align__(256) float          g_qkv [(size_t)NTOK * QKVC];
__device__ __align__(256) __nv_bfloat16  g_am1 [(size_t)NTOK * K1];
__device__ __align__(256) __nv_bfloat16  g_am2 [(size_t)NTOK * K2];
__device__ __align__(256) __nv_bfloat16  g_bm1 [(size_t)(3*HID+INTER) * K1];
__device__ __align__(256) __nv_bfloat16  g_bm2 [(size_t)HID * K2];

// ---------------- helpers ----------------
__device__ __forceinline__ uint32_t smem_u32(const void* p) {
    uint32_t a;
    asm("{ .reg .u64 t; cvta.to.shared.u64 t, %1; cvt.u32.u64 %0, t; }" : "=r"(a) : "l"(p));
    return a;
}
#define CPASYNC16(sa, gp) \
    asm volatile("cp.async.cg.shared.global [%0], [%1], 16;" :: "r"(sa), "l"(gp))
#define CP_COMMIT() asm volatile("cp.async.commit_group;" ::: "memory")
#define CP_WAIT1()  asm volatile("cp.async.wait_group 1;" ::: "memory")
#define CP_WAIT0()  asm volatile("cp.async.wait_group 0;" ::: "memory")
#define LDSM4(r0, r1, r2, r3, ad) \
    asm volatile("ldmatrix.sync.aligned.m8n8.x4.shared.b16 {%0,%1,%2,%3}, [%4];" \
                 : "=r"(r0), "=r"(r1), "=r"(r2), "=r"(r3) : "r"(ad))
#define MMA16816(d, a, b0, b1) \
    asm volatile("mma.sync.aligned.m16n8k16.row.col.f32.bf16.bf16.f32 " \
                 "{%0,%1,%2,%3}, {%4,%5,%6,%7}, {%8,%9}, {%0,%1,%2,%3};" \
                 : "+f"((d)[0]), "+f"((d)[1]), "+f"((d)[2]), "+f"((d)[3]) \
                 : "r"((a)[0]), "r"((a)[1]), "r"((a)[2]), "r"((a)[3]), "r"(b0), "r"(b1))

__device__ __forceinline__ void bf16_split(float v, __nv_bfloat16& hi, __nv_bfloat16& lo) {
    hi = __float2bfloat16(v);
    lo = __float2bfloat16(v - __bfloat162float(hi));
}

// ---------------- LayerNorm + A-triple emit for GEMM1 ----------------
__global__ void ln_kernel(const float* __restrict__ x,
                          const float* __restrict__ gamma,
                          const float* __restrict__ beta) {
    const int row = blockIdx.x, t = threadIdx.x;
    const float* xr = x + (size_t)row * HID;
    float v0 = xr[t], v1 = xr[t + 256], v2 = xr[t + 512];
    float s  = v0 + v1 + v2;
    float ss = v0 * v0 + v1 * v1 + v2 * v2;
    #pragma unroll
    for (int o = 16; o; o >>= 1) {
        s  += __shfl_xor_sync(0xffffffffu, s,  o);
        ss += __shfl_xor_sync(0xffffffffu, ss, o);
    }
    __shared__ float sh[18];
    if ((t & 31) == 0) { sh[t >> 5] = s; sh[(t >> 5) + 8] = ss; }
    __syncthreads();
    if (t == 0) {
        float S = 0.f, SS = 0.f;
        #pragma unroll
        for (int i = 0; i < 8; i++) { S += sh[i]; SS += sh[i + 8]; }
        float mu  = S * (1.0f / HID);
        float var = SS * (1.0f / HID) - mu * mu;
        sh[16] = mu;
        sh[17] = rsqrtf(var + 1e-5f);
    }
    __syncthreads();
    const float mu = sh[16], rs = sh[17];
    float* o = g_xn + (size_t)row * HID;
    __nv_bfloat16* a1 = g_am1 + (size_t)row * K1;
    #pragma unroll
    for (int g = 0; g < 3; g++) {
        const int c = t + g * 256;
        const float v = (g == 0 ? v0 : (g == 1 ? v1 : v2));
        const float y = (v - mu) * rs * gamma[c] + beta[c];
        o[c] = y;
        __nv_bfloat16 hi, lo; bf16_split(y, hi, lo);
        a1[3 * c]     = hi;   // A triple [hi, hi, lo]
        a1[3 * c + 1] = hi;
        a1[3 * c + 2] = lo;
    }
}

// ---------------- weight transpose + B-triple [hi, lo, hi] ----------------
// w[Kdim][Ndim] fp32 -> bm[Ndim][3*Kdim] bf16
__global__ void conv_w_kernel(const float* __restrict__ w, __nv_bfloat16* __restrict__ bm,
                              int Kdim, int Ndim) {
    __shared__ float tile[32][33];
    const int k0 = blockIdx.y << 5, n0 = blockIdx.x << 5;
    const int tx = threadIdx.x & 31, tr = threadIdx.x >> 5;
    #pragma unroll
    for (int r = 0; r < 32; r += 8)
        tile[tr + r][tx] = w[(size_t)(k0 + tr + r) * Ndim + n0 + tx];
    __syncthreads();
    const int nl = threadIdx.x & 31;
    const int kq = threadIdx.x >> 5;   // 4 k's per thread
    __align__(8) __nv_bfloat16 t[12];
    #pragma unroll
    for (int j = 0; j < 4; j++) {
        float v = tile[kq * 4 + j][nl];
        __nv_bfloat16 hi, lo; bf16_split(v, hi, lo);
        t[3*j] = hi; t[3*j+1] = lo; t[3*j+2] = hi;
    }
    unsigned long long* dp = (unsigned long long*)
        (bm + (size_t)(n0 + nl) * (3 * (size_t)Kdim) + 3 * (size_t)(k0 + kq * 4));
    const unsigned long long* ts = (const unsigned long long*)t;
    dp[0] = ts[0]; dp[1] = ts[1]; dp[2] = ts[2];
}

// ---------------- mma.sync GEMM: C[M,N] = A[M,K] * B[N,K]^T ----------------
// CTA tile 128x128, BK=64, 3-stage cp.async pipeline, epilogue via smem staging.
// mode 1: -> g_qkv fp32 (cols<2304) + gelu A-triples into outT
// mode 2: -> outF = acc + bias + resid
__global__ __launch_bounds__(256)
void gemm_mma(const __nv_bfloat16* __restrict__ A, const __nv_bfloat16* __restrict__ B,
              const float* __restrict__ bias, const float* __restrict__ resid,
              float* __restrict__ outF, float* __restrict__ outQKV,
              __nv_bfloat16* __restrict__ outT, int K, int mode)
{
    extern __shared__ char sm[];
    const uint32_t sb = smem_u32(sm);
    const int tid = threadIdx.x, lane = tid & 31, wid = tid >> 5;
    const int m0 = blockIdx.y << 7, n0 = blockIdx.x << 7;
    const int wm = wid & 3, wn = wid >> 2;

    // cp.async per-thread tile coords (4 x 16B chunks each for A and B)
    const int crow = tid >> 1;                 // reuse below for epilogue too

    auto load_stage = [&](int c, int s) {
        const int kc = c << 6;
        const __nv_bfloat16* Ab = A + (size_t)m0 * K + kc;
        const __nv_bfloat16* Bb = B + (size_t)n0 * K + kc;
        const uint32_t stA = sb + s * 32768;
        const uint32_t stB = stA + 16384;
        #pragma unroll
        for (int i = 0; i < 4; i++) {
            const int cid = tid + (i << 8);
            const int row = cid >> 3, ch = cid & 7;
            const uint32_t so = row * 128 + ((ch ^ (row & 7)) << 4);
            CPASYNC16(stA + so, Ab + (size_t)row * K + (ch << 3));
            CPASYNC16(stB + so, Bb + (size_t)row * K + (ch << 3));
        }
    };

    // ldmatrix lane bases
    const int la = lane & 7;
    const int rowA0 = wm * 32 + la + ((lane >> 3) & 1) * 8;   // + mf*16
    const int swA   = rowA0 & 7;
    const int cbA   = (lane >> 4) & 1;
    const int rowB0 = wn * 64 + la + ((lane >> 4) & 1) * 8;   // + nf2*16
    const int swB   = rowB0 & 7;
    const int cbB   = (lane >> 3) & 1;

    float acc[2][8][4];
    #pragma unroll
    for (int i = 0; i < 2; i++)
        #pragma unroll
        for (int j = 0; j < 8; j++)
            #pragma unroll
            for (int q = 0; q < 4; q++) acc[i][j][q] = 0.f;

    const int nc = K >> 6;
    load_stage(0, 0); CP_COMMIT();
    load_stage(1, 1); CP_COMMIT();

    for (int c = 0; c < nc; c++) {
        CP_WAIT1();
        __syncthreads();
        if (c + 2 < nc) load_stage(c + 2, (c + 2) % 3);
        CP_COMMIT();

        const uint32_t stA = sb + (c % 3) * 32768;
        const uint32_t stB = stA + 16384;
        #pragma unroll
        for (int kk = 0; kk < 4; kk++) {
            uint32_t a[2][4];
            #pragma unroll
            for (int mf = 0; mf < 2; mf++) {
                const uint32_t ad = stA + (rowA0 + mf * 16) * 128 + (((kk * 2 + cbA) ^ swA) << 4);
                LDSM4(a[mf][0], a[mf][1], a[mf][2], a[mf][3], ad);
            }
            uint32_t b[4][4];
            #pragma unroll
            for (int nf2 = 0; nf2 < 4; nf2++) {
                const uint32_t bd = stB + (rowB0 + nf2 * 16) * 128 + (((kk * 2 + cbB) ^ swB) << 4);
                LDSM4(b[nf2][0], b[nf2][1], b[nf2][2], b[nf2][3], bd);
            }
            #pragma unroll
            for (int mf = 0; mf < 2; mf++)
                #pragma unroll
                for (int nf = 0; nf < 8; nf++)
                    MMA16816(acc[mf][nf], a[mf], b[nf >> 1][(nf & 1) * 2], b[nf >> 1][(nf & 1) * 2 + 1]);
        }
        __syncthreads();
    }
    CP_WAIT0();
    __syncthreads();

    // stage C tile into smem, rows padded to 132 floats
    float* smC = (float*)sm;
    #pragma unroll
    for (int mf = 0; mf < 2; mf++)
        #pragma unroll
        for (int nf = 0; nf < 8; nf++)
            #pragma unroll
            for (int q = 0; q < 4; q++) {
                const int row = wm * 32 + mf * 16 + (lane >> 2) + ((q >> 1) << 3);
                const int col = wn * 64 + nf * 8 + ((lane & 3) << 1) + (q & 1);
                smC[row * 132 + col] = acc[mf][nf][q];
            }
    __syncthreads();

    // per-thread epilogue: row = tid/2, 64-col half = tid&1
    const int r  = tid >> 1, hf = tid & 1;
    const int mrow = m0 + r;
    const int nb   = n0 + hf * 64;
    const float* cr = smC + r * 132 + hf * 64;

    if (mode == 1) {
        if (nb < 3 * HID) {
            float* dst = outQKV + (size_t)mrow * QKVC + nb;
            #pragma unroll
            for (int q = 0; q < 16; q++) {
                float4 ov;
                ov.x = cr[q*4+0] + bias[nb+q*4+0];
                ov.y = cr[q*4+1] + bias[nb+q*4+1];
                ov.z = cr[q*4+2] + bias[nb+q*4+2];
                ov.w = cr[q*4+3] + bias[nb+q*4+3];
                *(float4*)(dst + q * 4) = ov;
            }
        } else {
            __align__(16) __nv_bfloat16 trip[192];
            #pragma unroll
            for (int i = 0; i < 64; i++) {
                float v = cr[i] + bias[nb + i];
                float u = v * (0.7978845608028654f + 0.0356774081f * v * v);
                v = 0.5f * v * (1.0f + tanhf(u));
                __nv_bfloat16 hi, lo; bf16_split(v, hi, lo);
                trip[3*i] = hi; trip[3*i+1] = hi; trip[3*i+2] = lo;
            }
            // combined col = HID + (nb - 3*HID) -> elem offset 3*nb - 6*HID
            uint4* dp = (uint4*)(outT + (size_t)mrow * K2 + (3 * nb - 6 * HID));
            const uint4* ts = (const uint4*)trip;
            #pragma unroll
            for (int j = 0; j < 24; j++) dp[j] = ts[j];
        }
    } else {
        float* dst = outF + (size_t)mrow * HID + nb;
        const float* rp = resid + (size_t)mrow * HID + nb;
        #pragma unroll
        for (int q = 0; q < 16; q++) {
            float4 rv = *(const float4*)(rp + q * 4);
            float4 ov;
            ov.x = cr[q*4+0] + bias[nb+q*4+0] + rv.x;
            ov.y = cr[q*4+1] + bias[nb+q*4+1] + rv.y;
            ov.z = cr[q*4+2] + bias[nb+q*4+2] + rv.z;
            ov.w = cr[q*4+3] + bias[nb+q*4+3] + rv.w;
            *(float4*)(dst + q * 4) = ov;
        }
    }
}

// ---------------- RoPE (in-place on g_qkv q,k cols) ----------------
__global__ void rope_kernel(const float* __restrict__ psin, const float* __restrict__ pcos) {
    const int idx = blockIdx.x * blockDim.x + threadIdx.x;   // NTOK * 768 pairs
    if (idx >= NTOK * 768) return;
    const int row = idx / 768;
    const int p   = idx - row * 768;
    const int col = p << 1;
    const int d   = col & (DH - 1);
    float2* ptr = (float2*)(g_qkv + (size_t)row * QKVC + col);
    const float2 eo = *ptr;
    const float c = pcos[row * DH + d];
    const float s = psin[row * DH + d];
    float2 r;
    r.x = eo.x * c - eo.y * s;
    r.y = eo.y * c + eo.x * s;
    *ptr = r;
}

// ---------------- Sliding-window attention (output -> A-triples of GEMM2) ----------------
__global__ __launch_bounds__(256, 1)
void attn_kernel(const int* __restrict__ plen) {
    __shared__ float Ks[64][DH];
    __shared__ float Vs[64][DH];
    const int h   = blockIdx.y;
    const int q0  = blockIdx.x << 8;
    const int tid = threadIdx.x;
    const int qi  = q0 + tid;
    const unsigned lm   = ~((unsigned)(*plen) - 1u);
    const unsigned qseg = (unsigned)qi & lm;

    float q[DH], acc[DH];
    {
        const float* qp = g_qkv + (size_t)qi * QKVC + h * DH;
        #pragma unroll
        for (int i = 0; i < 16; i++) *(float4*)&q[i * 4] = *(const float4*)(qp + i * 4);
    }
    #pragma unroll
    for (int i = 0; i < DH; i++) acc[i] = 0.f;
    float m = -1e30f, l = 0.f;

    const int r   = tid >> 2;
    const int sg  = (tid & 3) << 4;
    const int qw0 = q0 + (tid & ~31);

    for (int t = 0; t < 8; t++) {
        const int kbase = q0 - 256 + t * 64;
        __syncthreads();
        {
            const int kj = kbase + r;
            float4* dK = (float4*)&Ks[r][sg];
            float4* dV = (float4*)&Vs[r][sg];
            if (kj >= 0) {
                const float* kp = g_qkv + (size_t)kj * QKVC + HID + h * DH + sg;
                const float* vp = kp + HID;
                #pragma unroll
                for (int i = 0; i < 4; i++) dK[i] = ((const float4*)kp)[i];
                #pragma unroll
                for (int i = 0; i < 4; i++) dV[i] = ((const float4*)vp)[i];
            } else {
                const float4 z = make_float4(0.f, 0.f, 0.f, 0.f);
                #pragma unroll
                for (int i = 0; i < 4; i++) { dK[i] = z; dV[i] = z; }
            }
        }
        __syncthreads();
        int jlo = qw0 - 255 - kbase; if (jlo < 0) jlo = 0;
        int jhi = qw0 + 31  - kbase; if (jhi > 63) jhi = 63;
        for (int j = jlo; j <= jhi; j++) {
            const int kj  = kbase + j;
            const int dlt = qi - kj;
            const bool valid = (kj >= 0) & (dlt >= 0) & (dlt < WWIN) &
                               (((unsigned)kj & lm) == qseg);
            if (!valid) continue;
            float s = 0.f;
            #pragma unroll
            for (int d4 = 0; d4 < 16; d4++) {
                const float4 kv = *(const float4*)&Ks[j][d4 * 4];
                s += q[d4*4+0]*kv.x + q[d4*4+1]*kv.y + q[d4*4+2]*kv.z + q[d4*4+3]*kv.w;
            }
            s *= 0.125f;
            if (s > m) {
                const float sf = __expf(m - s);
                l *= sf;
                #pragma unroll
                for (int d = 0; d < DH; d++) acc[d] *= sf;
                m = s;
            }
            const float p = __expf(s - m);
            l += p;
            #pragma unroll
            for (int d4 = 0; d4 < 16; d4++) {
                const float4 vv = *(const float4*)&Vs[j][d4 * 4];
                acc[d4*4+0] = fmaf(p, vv.x, acc[d4*4+0]);
                acc[d4*4+1] = fmaf(p, vv.y, acc[d4*4+1]);
                acc[d4*4+2] = fmaf(p, vv.z, acc[d4*4+2]);
                acc[d4*4+3] = fmaf(p, vv.w, acc[d4*4+3]);
            }
        }
    }
    const float inv = 1.f / l;
    __nv_bfloat16* op = g_am2 + (size_t)qi * K2 + 192 * h;   // 3*(h*64)
    #pragma unroll
    for (int g = 0; g < 16; g++) {
        __align__(16) __nv_bfloat16 tbuf[12];
        #pragma unroll
        for (int j = 0; j < 4; j++) {
            float v = acc[g * 4 + j] * inv;
            __nv_bfloat16 hi, lo; bf16_split(v, hi, lo);
            tbuf[3*j] = hi; tbuf[3*j+1] = hi; tbuf[3*j+2] = lo;
        }
        unsigned long long* dp = (unsigned long long*)(op + 12 * g);
        const unsigned long long* ts = (const unsigned long long*)tbuf;
        dp[0] = ts[0]; dp[1] = ts[1]; dp[2] = ts[2];
    }
}

// ---------------- launch ----------------
extern "C" void kernel_launch(void* const* d_in, const int* in_sizes, int n_in,
                              void* d_out, int out_size) {
    const float* x        = (const float*)d_in[0];
    const float* psin     = (const float*)d_in[2];
    const float* pcos     = (const float*)d_in[3];
    const float* ln_scale = (const float*)d_in[4];
    const float* ln_off   = (const float*)d_in[5];
    const float* w_in     = (const float*)d_in[6];
    const float* b_in     = (const float*)d_in[7];
    const float* w_out    = (const float*)d_in[8];
    const float* b_out    = (const float*)d_in[9];
    const int*   plen     = (const int*)d_in[10];
    float* out = (float*)d_out;

    float *p_xn = nullptr, *p_qkv = nullptr;
    __nv_bfloat16 *p_am1 = nullptr, *p_am2 = nullptr, *p_bm1 = nullptr, *p_bm2 = nullptr;
    cudaGetSymbolAddress((void**)&p_xn,  g_xn);
    cudaGetSymbolAddress((void**)&p_qkv, g_qkv);
    cudaGetSymbolAddress((void**)&p_am1, g_am1);
    cudaGetSymbolAddress((void**)&p_am2, g_am2);
    cudaGetSymbolAddress((void**)&p_bm1, g_bm1);
    cudaGetSymbolAddress((void**)&p_bm2, g_bm2);

    static bool attr_set = false;
    const int gsmem = 3 * 32768;   // 96 KB: 3 load stages; reused as 128x132 C stage
    if (!attr_set) {
        cudaFuncSetAttribute(gemm_mma, cudaFuncAttributeMaxDynamicSharedMemorySize, gsmem);
        attr_set = true;
    }

    conv_w_kernel<<<dim3((3*HID+INTER)/32, HID/32), 256>>>(w_in,  p_bm1, HID, 3*HID+INTER);
    conv_w_kernel<<<dim3(HID/32, KC2/32),           256>>>(w_out, p_bm2, KC2, HID);

    ln_kernel<<<NTOK, 256>>>(x, ln_scale, ln_off);

    // GEMM1: [NTOK x 5376]
    gemm_mma<<<dim3((3*HID+INTER)/128, NTOK/128), 256, gsmem>>>(
        p_am1, p_bm1, b_in, nullptr, nullptr, p_qkv, p_am2, K1, 1);

    rope_kernel<<<(NTOK * 768) / 256, 256>>>(psin, pcos);

    attn_kernel<<<dim3(NCHUNK, NHEAD), 256>>>(plen);

    // GEMM2: out = xn + am2 @ bm2^T + b_out
    gemm_mma<<<dim3(HID/128, NTOK/128), 256, gsmem>>>(
        p_am2, p_bm2, b_out, p_xn, out, nullptr, nullptr, K2, 2);
}